// round 1
// baseline (speedup 1.0000x reference)
#include <cuda_runtime.h>
#include <cuda_bf16.h>
#include <math_constants.h>

// Problem constants (fixed by the dataset)
#define MAXN 100000
#define MAXE 1600000
#define IN_DIM 128
#define EDGE_DIM 16
#define NH 4
#define OUT_H 64
#define F_MLP 272   // 2*128+16

// ---------------- device scratch (static: no allocations allowed) -------------
__device__ int   g_rowptr[MAXN + 1];
__device__ float g_attn12[(size_t)MAXN * 8];           // [n][0:4]=attn1,[4:8]=attn2
__device__ float g_xobj[(size_t)MAXN * NH * IN_DIM];   // [n][h][128]
__device__ float g_xe[(size_t)MAXN * NH * EDGE_DIM];   // [n][h][16]
__device__ float g_h1[(size_t)MAXN * NH * OUT_H];      // [n][h][64]
__device__ float g_sum[NH * OUT_H];
__device__ float g_sqsum[NH * OUT_H];
__device__ float g_a[NH * OUT_H];                      // rsig*gamma
__device__ float g_c[NH * OUT_H];                      // beta - mu*rsig*gamma
__device__ float g_w1t[NH * F_MLP * OUT_H];            // [h][f][o]
__device__ float g_w2t[NH * OUT_H * OUT_H];            // [h][o][p]

// ---------------- f32x2 helpers (packed fp32, 2x FFMA throughput) -------------
__device__ __forceinline__ void ffma2(unsigned long long& d, unsigned long long a,
                                      unsigned long long b) {
    asm("fma.rn.f32x2 %0, %1, %2, %0;" : "+l"(d) : "l"(a), "l"(b));
}
__device__ __forceinline__ unsigned long long pack2(float lo, float hi) {
    unsigned long long r;
    asm("mov.b64 %0, {%1,%2};" : "=l"(r) : "f"(lo), "f"(hi));
    return r;
}
__device__ __forceinline__ void unpack2(unsigned long long v, float& lo, float& hi) {
    asm("mov.b64 {%0,%1}, %2;" : "=f"(lo), "=f"(hi) : "l"(v));
}

// ---------------- K0: CSR row pointers by binary search (row is sorted) -------
__global__ void k_rowptr(const int* __restrict__ row, int n, int e) {
    int i = blockIdx.x * blockDim.x + threadIdx.x;
    if (i > n) return;
    int lo = 0, hi = e;
    while (lo < hi) { int mid = (lo + hi) >> 1; if (row[mid] < i) lo = mid + 1; else hi = mid; }
    g_rowptr[i] = lo;
}

// ---------------- K1: per-node attention logits (attn1, attn2) ----------------
__global__ void k_nodelogits(const float* __restrict__ x, const float* __restrict__ a1w,
                             const float* __restrict__ a2w, int n) {
    __shared__ float sw[8 * 128];
    int tid = threadIdx.x;
    for (int i = tid; i < 512; i += 256) { sw[i] = a1w[i]; sw[512 + i] = a2w[i]; }
    __syncthreads();
    int warp = tid >> 5, lane = tid & 31;
    int nd = blockIdx.x * 8 + warp;
    if (nd >= n) return;
    float4 xv = *(const float4*)(x + (size_t)nd * 128 + lane * 4);
#pragma unroll
    for (int k = 0; k < 8; k++) {
        float4 wv = *(const float4*)(sw + k * 128 + lane * 4);
        float p = xv.x * wv.x + xv.y * wv.y + xv.z * wv.z + xv.w * wv.w;
        p += __shfl_xor_sync(0xffffffffu, p, 16);
        p += __shfl_xor_sync(0xffffffffu, p, 8);
        p += __shfl_xor_sync(0xffffffffu, p, 4);
        p += __shfl_xor_sync(0xffffffffu, p, 2);
        p += __shfl_xor_sync(0xffffffffu, p, 1);
        if (lane == 0) g_attn12[(size_t)nd * 8 + k] = p;
    }
}

// ---------------- K_pre: transpose small weights + zero BN stats --------------
__global__ void k_pre(const float* __restrict__ w1, const float* __restrict__ w2) {
    int h = blockIdx.x, tid = threadIdx.x;
    for (int i = tid; i < OUT_H * F_MLP; i += blockDim.x) {
        int o = i / F_MLP, f = i % F_MLP;
        g_w1t[(size_t)h * (F_MLP * OUT_H) + f * OUT_H + o] = w1[(size_t)h * (F_MLP * OUT_H) + i];
    }
    for (int i = tid; i < OUT_H * OUT_H; i += blockDim.x) {
        int p = i / OUT_H, o = i % OUT_H;
        g_w2t[h * 4096 + o * 64 + p] = w2[h * 4096 + i];
    }
    if (h == 0) { g_sum[tid] = 0.f; g_sqsum[tid] = 0.f; }   // blockDim == 256
}

// ---------------- K2: edge softmax + sparse aggregation (warp per node) -------
__device__ __forceinline__ void edge_logits(const float* __restrict__ ea,
                                            const float* s_aew, int e2, int ci,
                                            const float* a1h, float* lg) {
    const float4* ep = (const float4*)(ea + (size_t)e2 * 16);
    float4 q0 = ep[0], q1 = ep[1], q2 = ep[2], q3 = ep[3];
#pragma unroll
    for (int h = 0; h < 4; h++) {
        const float* wq = s_aew + h * 16;
        float d = q0.x * wq[0] + q0.y * wq[1] + q0.z * wq[2] + q0.w * wq[3]
                + q1.x * wq[4] + q1.y * wq[5] + q1.z * wq[6] + q1.w * wq[7]
                + q2.x * wq[8] + q2.y * wq[9] + q2.z * wq[10] + q2.w * wq[11]
                + q3.x * wq[12] + q3.y * wq[13] + q3.z * wq[14] + q3.w * wq[15];
        lg[h] = (a1h[h] + g_attn12[(size_t)ci * 8 + 4 + h] + d) * 0.125f;
    }
}

__global__ void __launch_bounds__(256) k_edge(const float* __restrict__ x,
                                              const int* __restrict__ col,
                                              const float* __restrict__ ea,
                                              const float* __restrict__ aew, int n) {
    __shared__ float s_aew[64];
    int tid = threadIdx.x;
    if (tid < 64) s_aew[tid] = aew[tid];
    __syncthreads();
    int nd = blockIdx.x * 8 + (tid >> 5);
    int lane = tid & 31;
    if (nd >= n) return;
    int start = g_rowptr[nd], end = g_rowptr[nd + 1];
    float a1h[4];
#pragma unroll
    for (int h = 0; h < 4; h++) a1h[h] = g_attn12[(size_t)nd * 8 + h];

    // Pass A: online softmax (lane-local, then warp combine)
    float m[4] = {-CUDART_INF_F, -CUDART_INF_F, -CUDART_INF_F, -CUDART_INF_F};
    float s[4] = {0.f, 0.f, 0.f, 0.f};
    for (int base = start; base < end; base += 32) {
        int e2 = base + lane;
        if (e2 < end) {
            int ci = col[e2];
            float lg[4];
            edge_logits(ea, s_aew, e2, ci, a1h, lg);
#pragma unroll
            for (int h = 0; h < 4; h++) {
                if (lg[h] > m[h]) { s[h] = s[h] * __expf(m[h] - lg[h]) + 1.f; m[h] = lg[h]; }
                else              { s[h] += __expf(lg[h] - m[h]); }
            }
        }
    }
#pragma unroll
    for (int off = 16; off >= 1; off >>= 1) {
#pragma unroll
        for (int h = 0; h < 4; h++) {
            float om = __shfl_xor_sync(0xffffffffu, m[h], off);
            float os = __shfl_xor_sync(0xffffffffu, s[h], off);
            float nm = fmaxf(m[h], om);
            float t = (s[h] > 0.f ? s[h] * __expf(m[h] - nm) : 0.f)
                    + (os > 0.f ? os * __expf(om - nm) : 0.f);
            m[h] = nm; s[h] = t;
        }
    }
    float inv[4];
#pragma unroll
    for (int h = 0; h < 4; h++) inv[h] = 1.f / (s[h] + 1e-16f);

    // Pass B: weighted aggregation of x[col] (128d) and edge_attr (16d)
    float4 acc[4];
#pragma unroll
    for (int h = 0; h < 4; h++) acc[h] = make_float4(0.f, 0.f, 0.f, 0.f);
    float acce[4] = {0.f, 0.f, 0.f, 0.f};

    for (int base = start; base < end; base += 32) {
        int e2 = base + lane;
        int ci = 0;
        float w[4] = {0.f, 0.f, 0.f, 0.f};
        if (e2 < end) {
            ci = col[e2];
            float lg[4];
            edge_logits(ea, s_aew, e2, ci, a1h, lg);
#pragma unroll
            for (int h = 0; h < 4; h++) w[h] = __expf(lg[h] - m[h]) * inv[h];
        }
        int cnt = min(32, end - base);
        int cj = __shfl_sync(0xffffffffu, ci, 0);
        float4 xv = *(const float4*)(x + (size_t)cj * 128 + lane * 4);
        for (int j = 0; j < cnt; j++) {
            float w0 = __shfl_sync(0xffffffffu, w[0], j);
            float w1_ = __shfl_sync(0xffffffffu, w[1], j);
            float w2_ = __shfl_sync(0xffffffffu, w[2], j);
            float w3_ = __shfl_sync(0xffffffffu, w[3], j);
            float4 cur = xv;
            if (j + 1 < cnt) {
                int cn = __shfl_sync(0xffffffffu, ci, j + 1);
                xv = *(const float4*)(x + (size_t)cn * 128 + lane * 4);
            }
            acc[0].x += w0 * cur.x; acc[0].y += w0 * cur.y; acc[0].z += w0 * cur.z; acc[0].w += w0 * cur.w;
            acc[1].x += w1_ * cur.x; acc[1].y += w1_ * cur.y; acc[1].z += w1_ * cur.z; acc[1].w += w1_ * cur.w;
            acc[2].x += w2_ * cur.x; acc[2].y += w2_ * cur.y; acc[2].z += w2_ * cur.z; acc[2].w += w2_ * cur.w;
            acc[3].x += w3_ * cur.x; acc[3].y += w3_ * cur.y; acc[3].z += w3_ * cur.z; acc[3].w += w3_ * cur.w;
            if (lane < 16) {
                float eav = ea[(size_t)(base + j) * 16 + lane];
                acce[0] += w0 * eav; acce[1] += w1_ * eav; acce[2] += w2_ * eav; acce[3] += w3_ * eav;
            }
        }
    }
    size_t ob = (size_t)nd * (NH * IN_DIM);
#pragma unroll
    for (int h = 0; h < 4; h++)
        *(float4*)(g_xobj + ob + h * 128 + lane * 4) = acc[h];
    if (lane < 16) {
#pragma unroll
        for (int h = 0; h < 4; h++)
            g_xe[(size_t)nd * 64 + h * 16 + lane] = acce[h];
    }
}

// ---------------- K3: first MLP layer + ReLU + BN partial stats ---------------
// tile: 128 nodes x 64 outs, one head per blockIdx.y; f32x2 over output pairs.
#define K3_SMEM ((F_MLP * 64 + 128 * 273 + 2048) * 4)
__global__ void __launch_bounds__(512) k_mlp1(const float* __restrict__ x,
                                              const float* __restrict__ b1, int n) {
    extern __shared__ float smem[];
    float* sW = smem;                       // [f][64]
    float* sF = smem + F_MLP * 64;          // [128][273]
    float* sRed = sF + 128 * 273;           // [16][64] sum + [16][64] sqsum
    int h = blockIdx.y;
    int n0 = blockIdx.x * 128;
    int tid = threadIdx.x;

    const float* w1t = g_w1t + (size_t)h * (F_MLP * 64);
    for (int i = tid; i < F_MLP * 64; i += 512) sW[i] = w1t[i];
    for (int i = tid; i < 128 * F_MLP; i += 512) {
        int nl = i / F_MLP, f = i - nl * F_MLP;
        int nd = n0 + nl;
        float v = 0.f;
        if (nd < n) {
            if (f < 128)      v = x[(size_t)nd * 128 + f];
            else if (f < 256) v = g_xobj[(size_t)nd * 512 + h * 128 + (f - 128)];
            else              v = g_xe[(size_t)nd * 64 + h * 16 + (f - 256)];
        }
        sF[nl * 273 + f] = v;
    }
    __syncthreads();

    int to = tid & 15, tn = tid >> 4;       // tn: 0..31 -> 4 nodes each, to: 4 outs
    unsigned long long acc[4][2];
#pragma unroll
    for (int i = 0; i < 4; i++) { acc[i][0] = 0ull; acc[i][1] = 0ull; }
    const float* fbase = sF + tn * 4 * 273;
    for (int f = 0; f < F_MLP; f++) {
        float4 wv = *(const float4*)(sW + f * 64 + to * 4);
        unsigned long long w01 = pack2(wv.x, wv.y);
        unsigned long long w23 = pack2(wv.z, wv.w);
#pragma unroll
        for (int i = 0; i < 4; i++) {
            float fv = fbase[i * 273 + f];
            unsigned long long fvv = pack2(fv, fv);
            ffma2(acc[i][0], fvv, w01);
            ffma2(acc[i][1], fvv, w23);
        }
    }
    float4 b1q = *(const float4*)(b1 + h * 64 + to * 4);
    float ps[4] = {0.f, 0.f, 0.f, 0.f}, pq[4] = {0.f, 0.f, 0.f, 0.f};
#pragma unroll
    for (int i = 0; i < 4; i++) {
        float v0, v1, v2, v3;
        unpack2(acc[i][0], v0, v1); unpack2(acc[i][1], v2, v3);
        v0 = fmaxf(v0 + b1q.x, 0.f); v1 = fmaxf(v1 + b1q.y, 0.f);
        v2 = fmaxf(v2 + b1q.z, 0.f); v3 = fmaxf(v3 + b1q.w, 0.f);
        int nd = n0 + tn * 4 + i;
        if (nd < n) {
            *(float4*)(g_h1 + ((size_t)nd * 4 + h) * 64 + to * 4) = make_float4(v0, v1, v2, v3);
            ps[0] += v0; ps[1] += v1; ps[2] += v2; ps[3] += v3;
            pq[0] += v0 * v0; pq[1] += v1 * v1; pq[2] += v2 * v2; pq[3] += v3 * v3;
        }
    }
    // reduce stats: shfl over tn parity, then smem over 16 warps, then 128 atomics
#pragma unroll
    for (int j = 0; j < 4; j++) {
        ps[j] += __shfl_xor_sync(0xffffffffu, ps[j], 16);
        pq[j] += __shfl_xor_sync(0xffffffffu, pq[j], 16);
    }
    int warp = tid >> 5;
    if ((tid & 31) < 16) {
#pragma unroll
        for (int j = 0; j < 4; j++) {
            sRed[warp * 64 + to * 4 + j] = ps[j];
            sRed[1024 + warp * 64 + to * 4 + j] = pq[j];
        }
    }
    __syncthreads();
    if (tid < 64) {
        float s1 = 0.f, s2 = 0.f;
        for (int wv2 = 0; wv2 < 16; wv2++) {
            s1 += sRed[wv2 * 64 + tid];
            s2 += sRed[1024 + wv2 * 64 + tid];
        }
        atomicAdd(&g_sum[h * 64 + tid], s1);
        atomicAdd(&g_sqsum[h * 64 + tid], s2);
    }
}

// ---------------- K4: finalize BN stats into a*x + c form ---------------------
__global__ void k_stats(const float* __restrict__ gamma, const float* __restrict__ beta, int n) {
    int i = threadIdx.x;   // 256
    float inv_n = 1.f / (float)n;
    float mu = g_sum[i] * inv_n;
    float var = g_sqsum[i] * inv_n - mu * mu;
    float r = rsqrtf(var + 1e-5f);
    float a = r * gamma[i];
    g_a[i] = a;
    g_c[i] = beta[i] - mu * a;
}

// ---------------- K5: BN apply + second MLP layer -----------------------------
#define K5_SMEM ((4096 + 128 * 65) * 4)
__global__ void __launch_bounds__(512) k_mlp2(const float* __restrict__ b2,
                                              float* __restrict__ out, int n) {
    extern __shared__ float smem[];
    float* sW = smem;              // [o][64]
    float* sH = smem + 4096;       // [128][65]
    int h = blockIdx.y;
    int n0 = blockIdx.x * 128;
    int tid = threadIdx.x;
    for (int i = tid; i < 4096; i += 512) sW[i] = g_w2t[h * 4096 + i];
    for (int i = tid; i < 128 * 64; i += 512) {
        int nl = i >> 6, o = i & 63;
        int nd = n0 + nl;
        float v = 0.f;
        if (nd < n) v = g_h1[((size_t)nd * 4 + h) * 64 + o] * g_a[h * 64 + o] + g_c[h * 64 + o];
        sH[nl * 65 + o] = v;
    }
    __syncthreads();
    int to = tid & 15, tn = tid >> 4;
    unsigned long long acc[4][2];
#pragma unroll
    for (int i = 0; i < 4; i++) { acc[i][0] = 0ull; acc[i][1] = 0ull; }
    const float* hbase = sH + tn * 4 * 65;
#pragma unroll 4
    for (int o = 0; o < 64; o++) {
        float4 wv = *(const float4*)(sW + o * 64 + to * 4);
        unsigned long long w01 = pack2(wv.x, wv.y);
        unsigned long long w23 = pack2(wv.z, wv.w);
#pragma unroll
        for (int i = 0; i < 4; i++) {
            float fv = hbase[i * 65 + o];
            unsigned long long fvv = pack2(fv, fv);
            ffma2(acc[i][0], fvv, w01);
            ffma2(acc[i][1], fvv, w23);
        }
    }
    float4 b2q = *(const float4*)(b2 + h * 64 + to * 4);
#pragma unroll
    for (int i = 0; i < 4; i++) {
        int nd = n0 + tn * 4 + i;
        if (nd < n) {
            float v0, v1, v2, v3;
            unpack2(acc[i][0], v0, v1); unpack2(acc[i][1], v2, v3);
            *(float4*)(out + (size_t)nd * 256 + h * 64 + to * 4) =
                make_float4(v0 + b2q.x, v1 + b2q.y, v2 + b2q.z, v3 + b2q.w);
        }
    }
}

// ---------------- launch ------------------------------------------------------
extern "C" void kernel_launch(void* const* d_in, const int* in_sizes, int n_in,
                              void* d_out, int out_size) {
    const float* x     = (const float*)d_in[0];
    const int*   row   = (const int*)d_in[1];
    const int*   col   = (const int*)d_in[2];
    const float* ea    = (const float*)d_in[3];
    const float* a1w   = (const float*)d_in[4];
    const float* a2w   = (const float*)d_in[5];
    const float* aew   = (const float*)d_in[6];
    const float* w1    = (const float*)d_in[7];
    const float* b1    = (const float*)d_in[8];
    const float* gamma = (const float*)d_in[9];
    const float* beta  = (const float*)d_in[10];
    const float* w2    = (const float*)d_in[11];
    const float* b2    = (const float*)d_in[12];
    float* out = (float*)d_out;

    int n = in_sizes[0] / IN_DIM;
    int e = in_sizes[1];

    cudaFuncSetAttribute(k_mlp1, cudaFuncAttributeMaxDynamicSharedMemorySize, K3_SMEM);
    cudaFuncSetAttribute(k_mlp2, cudaFuncAttributeMaxDynamicSharedMemorySize, K5_SMEM);

    k_rowptr<<<(n + 256) / 256, 256>>>(row, n, e);
    k_nodelogits<<<(n + 7) / 8, 256>>>(x, a1w, a2w, n);
    k_pre<<<4, 256>>>(w1, w2);
    k_edge<<<(n + 7) / 8, 256>>>(x, col, ea, aew, n);
    dim3 g3((n + 127) / 128, 4);
    k_mlp1<<<g3, 512, K3_SMEM>>>(x, b1, n);
    k_stats<<<1, 256>>>(gamma, beta, n);
    k_mlp2<<<g3, 512, K5_SMEM>>>(b2, out, n);
}